// round 1
// baseline (speedup 1.0000x reference)
#include <cuda_runtime.h>
#include <cuda_bf16.h>
#include <cstdint>

// Problem constants
#define Bb 4
#define Ss 2048
#define Dd 1024
#define Hh 16
#define DHd 64

// Scratch (allocated at module load, allowed)
__device__ float g_qkv[(size_t)Bb * Ss * 3 * Dd];   // [B*S, 3D] = [8192, 3072]
__device__ float g_attn[(size_t)Bb * Ss * Dd];      // [B*S, D]  = [8192, 1024]

// ---------------------------------------------------------------------------
// SGEMM with fused bias: C[M,N] = A[M,K] @ W[K,N] + bias[N]
// 128x128 tile, BK=8, 256 threads, 8x8 microtile per thread.
// M,N,K all multiples of 128/128/8 for our shapes — no bounds checks.
// ---------------------------------------------------------------------------
__global__ void __launch_bounds__(256) sgemm_bias(
    const float* __restrict__ A, const float* __restrict__ W,
    const float* __restrict__ bias, float* __restrict__ C,
    int M, int N, int K)
{
    __shared__ float As[8][128];
    __shared__ float Bs[8][128];

    const int tid = threadIdx.x;
    const int tx = tid & 15;        // 0..15 (N dim)
    const int ty = tid >> 4;        // 0..15 (M dim)
    const int row0 = blockIdx.y * 128;
    const int col0 = blockIdx.x * 128;

    // A-tile load mapping: 128 rows x 8 cols, each thread a float4
    const int arow = tid >> 1;            // 0..127
    const int acol = (tid & 1) << 2;      // 0 or 4
    // B-tile load mapping: 8 rows x 128 cols, each thread a float4
    const int brow = tid >> 5;            // 0..7
    const int bcol = (tid & 31) << 2;     // 0..124

    float acc[8][8];
#pragma unroll
    for (int i = 0; i < 8; i++)
#pragma unroll
        for (int j = 0; j < 8; j++) acc[i][j] = 0.f;

    const float* Ab = A + (size_t)(row0 + arow) * K + acol;
    const float* Wb = W + (size_t)brow * N + col0 + bcol;

    for (int k0 = 0; k0 < K; k0 += 8) {
        float4 av = *(const float4*)(Ab + k0);
        float4 bv = *(const float4*)(Wb + (size_t)k0 * N);
        As[acol + 0][arow] = av.x;
        As[acol + 1][arow] = av.y;
        As[acol + 2][arow] = av.z;
        As[acol + 3][arow] = av.w;
        *(float4*)&Bs[brow][bcol] = bv;
        __syncthreads();

#pragma unroll
        for (int kk = 0; kk < 8; kk++) {
            float4 a0 = *(const float4*)&As[kk][ty * 8];
            float4 a1 = *(const float4*)&As[kk][ty * 8 + 4];
            float4 b0 = *(const float4*)&Bs[kk][tx * 8];
            float4 b1 = *(const float4*)&Bs[kk][tx * 8 + 4];
            float a[8] = {a0.x, a0.y, a0.z, a0.w, a1.x, a1.y, a1.z, a1.w};
            float bb[8] = {b0.x, b0.y, b0.z, b0.w, b1.x, b1.y, b1.z, b1.w};
#pragma unroll
            for (int i = 0; i < 8; i++)
#pragma unroll
                for (int j = 0; j < 8; j++)
                    acc[i][j] = fmaf(a[i], bb[j], acc[i][j]);
        }
        __syncthreads();
    }

    // Epilogue: add bias, store
#pragma unroll
    for (int i = 0; i < 8; i++) {
        const int r = row0 + ty * 8 + i;
#pragma unroll
        for (int j4 = 0; j4 < 8; j4 += 4) {
            const int c = col0 + tx * 8 + j4;
            float4 bb = *(const float4*)(bias + c);
            float4 o;
            o.x = acc[i][j4 + 0] + bb.x;
            o.y = acc[i][j4 + 1] + bb.y;
            o.z = acc[i][j4 + 2] + bb.z;
            o.w = acc[i][j4 + 3] + bb.w;
            *(float4*)(C + (size_t)r * N + c) = o;
        }
    }
}

// ---------------------------------------------------------------------------
// Flash attention (no 1/sqrt(dk) scaling, per reference).
// qkv layout: [B, S, 3D]; per (b,h): q = qkv[b,s, h*64 + .], k at +D, v at +2D.
// Block: 64 queries x full key sweep in 64-key tiles. 256 threads.
// Thread (ty,tx): ty -> 4 query rows, tx -> 4 key cols / 4 output dims.
// Row groups of 16 threads (same ty) reduce via shfl (width 16).
// ---------------------------------------------------------------------------
__global__ void __launch_bounds__(256) flash_attn(
    const float* __restrict__ qkv, float* __restrict__ out)
{
    extern __shared__ float sm[];
    float* Qt = sm;            // [d][r]  (transposed) 4096 floats
    float* Kt = sm + 4096;     // [d][c]  (transposed)
    float* Vs = sm + 8192;     // [c][d]
    float* Ps = sm + 12288;    // [r][c]

    const int tid = threadIdx.x;
    const int tx = tid & 15;
    const int ty = tid >> 4;
    const int qt = blockIdx.x;            // query tile 0..31
    const int bh = blockIdx.y;            // 0..63
    const int b = bh >> 4;
    const int h = bh & 15;
    const int R = ty * 4;                 // query row base
    const int Cc = tx * 4;                // key col / out dim base

    const size_t ROW = 3 * Dd;
    const float* base = qkv + (size_t)b * Ss * ROW + h * DHd;

    // Load Q tile transposed: Qt[d*64 + r] = Q[r][d]
    {
        const int r = tid >> 2;
        const int quad = tid & 3;
        const float* qrow = base + (size_t)(qt * 64 + r) * ROW;
#pragma unroll
        for (int u = 0; u < 4; u++) {
            const int d0 = quad * 16 + u * 4;
            float4 v = *(const float4*)(qrow + d0);
            Qt[(d0 + 0) * 64 + r] = v.x;
            Qt[(d0 + 1) * 64 + r] = v.y;
            Qt[(d0 + 2) * 64 + r] = v.z;
            Qt[(d0 + 3) * 64 + r] = v.w;
        }
    }

    float oacc[4][4];
    float m[4], l[4];
#pragma unroll
    for (int i = 0; i < 4; i++) {
        m[i] = -1e30f;
        l[i] = 0.f;
#pragma unroll
        for (int j = 0; j < 4; j++) oacc[i][j] = 0.f;
    }

    for (int kt = 0; kt < Ss / 64; kt++) {
        __syncthreads();   // previous iteration's consumers done with Kt/Vs
        // Load K tile (transposed) and V tile (natural)
        {
            const int r = tid >> 2;
            const int quad = tid & 3;
            const float* krow = base + (size_t)(kt * 64 + r) * ROW + Dd;
            const float* vrow = base + (size_t)(kt * 64 + r) * ROW + 2 * Dd;
#pragma unroll
            for (int u = 0; u < 4; u++) {
                const int d0 = quad * 16 + u * 4;
                float4 kv = *(const float4*)(krow + d0);
                Kt[(d0 + 0) * 64 + r] = kv.x;
                Kt[(d0 + 1) * 64 + r] = kv.y;
                Kt[(d0 + 2) * 64 + r] = kv.z;
                Kt[(d0 + 3) * 64 + r] = kv.w;
                *(float4*)&Vs[r * 64 + d0] = *(const float4*)(vrow + d0);
            }
        }
        __syncthreads();

        // Scores: s[i][j] = sum_d Q[R+i][d] * K[Cc+j][d]
        float s[4][4];
#pragma unroll
        for (int i = 0; i < 4; i++)
#pragma unroll
            for (int j = 0; j < 4; j++) s[i][j] = 0.f;

#pragma unroll 4
        for (int d = 0; d < 64; d++) {
            float4 q = *(const float4*)&Qt[d * 64 + R];
            float4 k = *(const float4*)&Kt[d * 64 + Cc];
            float qa[4] = {q.x, q.y, q.z, q.w};
            float ka[4] = {k.x, k.y, k.z, k.w};
#pragma unroll
            for (int i = 0; i < 4; i++)
#pragma unroll
                for (int j = 0; j < 4; j++)
                    s[i][j] = fmaf(qa[i], ka[j], s[i][j]);
        }

        // Online softmax per row (16-thread row groups, shfl width 16)
#pragma unroll
        for (int i = 0; i < 4; i++) {
            float mx = fmaxf(fmaxf(s[i][0], s[i][1]), fmaxf(s[i][2], s[i][3]));
#pragma unroll
            for (int off = 8; off > 0; off >>= 1)
                mx = fmaxf(mx, __shfl_xor_sync(0xffffffffu, mx, off));
            const float mnew = fmaxf(m[i], mx);
            const float corr = __expf(m[i] - mnew);
            float p0 = __expf(s[i][0] - mnew);
            float p1 = __expf(s[i][1] - mnew);
            float p2 = __expf(s[i][2] - mnew);
            float p3 = __expf(s[i][3] - mnew);
            float rs = p0 + p1 + p2 + p3;
#pragma unroll
            for (int off = 8; off > 0; off >>= 1)
                rs += __shfl_xor_sync(0xffffffffu, rs, off);
            l[i] = l[i] * corr + rs;
            m[i] = mnew;
#pragma unroll
            for (int j = 0; j < 4; j++) oacc[i][j] *= corr;
            *(float4*)&Ps[(R + i) * 64 + Cc] = make_float4(p0, p1, p2, p3);
        }
        __syncwarp();   // Ps produced/consumed within the same warp's row groups

        // PV: oacc[i][j] += sum_c P[R+i][c] * V[c][Cc+j]
#pragma unroll 4
        for (int c = 0; c < 64; c++) {
            float4 v = *(const float4*)&Vs[c * 64 + Cc];
            float va[4] = {v.x, v.y, v.z, v.w};
            float pr[4];
#pragma unroll
            for (int i = 0; i < 4; i++) pr[i] = Ps[(R + i) * 64 + c];
#pragma unroll
            for (int i = 0; i < 4; i++)
#pragma unroll
                for (int j = 0; j < 4; j++)
                    oacc[i][j] = fmaf(pr[i], va[j], oacc[i][j]);
        }
    }

    // Write merged-head output: out[b, qt*64+R+i, h*64 + Cc + j]
#pragma unroll
    for (int i = 0; i < 4; i++) {
        const float inv = 1.f / l[i];
        float4 o;
        o.x = oacc[i][0] * inv;
        o.y = oacc[i][1] * inv;
        o.z = oacc[i][2] * inv;
        o.w = oacc[i][3] * inv;
        const size_t orow = ((size_t)b * Ss + qt * 64 + R + i) * Dd + h * DHd + Cc;
        *(float4*)(out + orow) = o;
    }
}

// ---------------------------------------------------------------------------
extern "C" void kernel_launch(void* const* d_in, const int* in_sizes, int n_in,
                              void* d_out, int out_size)
{
    (void)in_sizes; (void)n_in; (void)out_size;
    const float* x  = (const float*)d_in[0];   // [B,S,D]
    const float* w1 = (const float*)d_in[1];   // [D,3D]
    const float* b1 = (const float*)d_in[2];   // [3D]
    const float* w2 = (const float*)d_in[3];   // [D,D]
    const float* b2 = (const float*)d_in[4];   // [D]
    float* out = (float*)d_out;                // [B,S,D]

    float* qkv;  cudaGetSymbolAddress((void**)&qkv,  g_qkv);
    float* attn; cudaGetSymbolAddress((void**)&attn, g_attn);

    // 64 KB dynamic smem for flash_attn
    cudaFuncSetAttribute(flash_attn, cudaFuncAttributeMaxDynamicSharedMemorySize, 65536);

    const int M = Bb * Ss;           // 8192
    // 1) QKV projection: [8192,1024] @ [1024,3072] + b1
    sgemm_bias<<<dim3(3 * Dd / 128, M / 128), 256>>>(x, w1, b1, qkv, M, 3 * Dd, Dd);
    // 2) Attention
    flash_attn<<<dim3(Ss / 64, Bb * Hh), 256, 65536>>>(qkv, attn);
    // 3) Output projection: [8192,1024] @ [1024,1024] + b2
    sgemm_bias<<<dim3(Dd / 128, M / 128), 256>>>(attn, w2, b2, out, M, Dd, Dd);
}

// round 3
// speedup vs baseline: 1.2796x; 1.2796x over previous
#include <cuda_runtime.h>
#include <cuda_bf16.h>
#include <cstdint>

// Problem constants
#define Bb 4
#define Ss 2048
#define Dd 1024
#define Hh 16
#define DHd 64

// Scratch
__device__ float g_qkv[(size_t)Bb * Ss * 3 * Dd];   // [8192, 3072]
__device__ float g_attn[(size_t)Bb * Ss * Dd];      // [8192, 1024]

// ---------------------------------------------------------------------------
// Helpers (portable: ldmatrix sm_75+, mma.sync bf16 sm_80+)
// ---------------------------------------------------------------------------
__device__ __forceinline__ uint32_t s2u(const void* p) {
    uint32_t a;
    asm("{ .reg .u64 t; cvta.to.shared.u64 t, %1; cvt.u32.u64 %0, t; }" : "=r"(a) : "l"(p));
    return a;
}

__device__ __forceinline__ void ldmx4(uint32_t* r, uint32_t addr) {
    asm volatile("ldmatrix.sync.aligned.m8n8.x4.shared.b16 {%0,%1,%2,%3}, [%4];"
        : "=r"(r[0]), "=r"(r[1]), "=r"(r[2]), "=r"(r[3]) : "r"(addr));
}

__device__ __forceinline__ void mma_bf16(float* c, const uint32_t* a, const uint32_t* b) {
    asm volatile("mma.sync.aligned.m16n8k16.row.col.f32.bf16.bf16.f32 "
        "{%0,%1,%2,%3}, {%4,%5,%6,%7}, {%8,%9}, {%0,%1,%2,%3};"
        : "+f"(c[0]), "+f"(c[1]), "+f"(c[2]), "+f"(c[3])
        : "r"(a[0]), "r"(a[1]), "r"(a[2]), "r"(a[3]), "r"(b[0]), "r"(b[1]));
}

// fp32 pair -> packed hi bf16x2 and lo bf16x2 (hi = rn(f), lo = rn(f - hi))
__device__ __forceinline__ void cvt_pack(float f0, float f1, uint32_t& hi, uint32_t& lo) {
    __nv_bfloat16 h0 = __float2bfloat16(f0);
    __nv_bfloat16 h1 = __float2bfloat16(f1);
    __nv_bfloat16 l0 = __float2bfloat16(f0 - __bfloat162float(h0));
    __nv_bfloat16 l1 = __float2bfloat16(f1 - __bfloat162float(h1));
    hi = ((uint32_t)__bfloat16_as_ushort(h1) << 16) | (uint32_t)__bfloat16_as_ushort(h0);
    lo = ((uint32_t)__bfloat16_as_ushort(l1) << 16) | (uint32_t)__bfloat16_as_ushort(l0);
}

// ---------------------------------------------------------------------------
// Tensor-core GEMM via mma.sync: C[M,N] = A[M,K] @ W[K,N] + bias[N] (fp32 io).
// CTA 128x128, BK=32, 8 warps (2m x 4n), each warp 64x32 via m16n8k16 tiles.
// fp32 emulated with bf16 hi/lo split: 3 MMAs per k-step.
// smem tiles padded to stride 40 bf16 (80B) -> conflict-free ldmatrix.
// ---------------------------------------------------------------------------
#define BK 32
#define SA 40            // padded bf16 stride (elements)
#define TILE_B (128 * SA * 2)            // 10240 bytes per tile
#define OFF_AHI 0
#define OFF_ALO (TILE_B)
#define OFF_BHI (2 * TILE_B)
#define OFF_BLO (3 * TILE_B)
#define OFF_STG (4 * TILE_B)             // fp32 stage: 32 x 132
#define GEMM_SMEM (OFF_STG + BK * 132 * 4)   // 57856

__global__ void __launch_bounds__(256, 2) gemm_mma(
    const float* __restrict__ A, const float* __restrict__ W,
    const float* __restrict__ bias, float* __restrict__ C,
    int M, int N, int K)
{
    extern __shared__ char smem[];
    char* pAhi = smem + OFF_AHI;
    char* pAlo = smem + OFF_ALO;
    char* pBhi = smem + OFF_BHI;
    char* pBlo = smem + OFF_BLO;
    float* stage = (float*)(smem + OFF_STG);

    const int tid = threadIdx.x;
    const int lane = tid & 31;
    const int warp = tid >> 5;
    const int wm = warp >> 2;        // 0..1
    const int wn = warp & 3;         // 0..3
    const int row0 = blockIdx.y * 128;
    const int col0 = blockIdx.x * 128;

    const uint32_t uAhi = s2u(pAhi);
    const uint32_t uAlo = s2u(pAlo);
    const uint32_t uBhi = s2u(pBhi);
    const uint32_t uBlo = s2u(pBlo);

    float acc[4][4][4];
#pragma unroll
    for (int i = 0; i < 4; i++)
#pragma unroll
        for (int j = 0; j < 4; j++)
#pragma unroll
            for (int e = 0; e < 4; e++) acc[i][j][e] = 0.f;

    // ldmatrix per-lane address offsets (same formula for A and B tiles)
    const uint32_t fragoff = (uint32_t)(lane & 15) * (SA * 2) + (uint32_t)(lane >> 4) * 16;

    const int nchunks = K / BK;
    for (int kc = 0; kc < nchunks; kc++) {
        __syncthreads();   // previous compute done reading Asm/Bsm; stage free

        // ---- A tile: 128 rows x 32 k, fp32 -> hi/lo bf16 ----
        {
            const int r = tid >> 1;
            const int kh = (tid & 1) * 16;
            const float* src = A + (size_t)(row0 + r) * K + kc * BK + kh;
            float4 v0 = *(const float4*)(src + 0);
            float4 v1 = *(const float4*)(src + 4);
            float4 v2 = *(const float4*)(src + 8);
            float4 v3 = *(const float4*)(src + 12);
            uint32_t hi[8], lo[8];
            cvt_pack(v0.x, v0.y, hi[0], lo[0]);
            cvt_pack(v0.z, v0.w, hi[1], lo[1]);
            cvt_pack(v1.x, v1.y, hi[2], lo[2]);
            cvt_pack(v1.z, v1.w, hi[3], lo[3]);
            cvt_pack(v2.x, v2.y, hi[4], lo[4]);
            cvt_pack(v2.z, v2.w, hi[5], lo[5]);
            cvt_pack(v3.x, v3.y, hi[6], lo[6]);
            cvt_pack(v3.z, v3.w, hi[7], lo[7]);
            const uint32_t off = (uint32_t)r * (SA * 2) + (uint32_t)kh * 2;
            *(uint4*)(pAhi + off)      = make_uint4(hi[0], hi[1], hi[2], hi[3]);
            *(uint4*)(pAhi + off + 16) = make_uint4(hi[4], hi[5], hi[6], hi[7]);
            *(uint4*)(pAlo + off)      = make_uint4(lo[0], lo[1], lo[2], lo[3]);
            *(uint4*)(pAlo + off + 16) = make_uint4(lo[4], lo[5], lo[6], lo[7]);
        }

        // ---- W stage: 32 k x 128 n fp32, coalesced ----
#pragma unroll
        for (int u = 0; u < 4; u++) {
            const int id = u * 256 + tid;
            const int r = id >> 5;
            const int c4 = (id & 31) * 4;
            float4 v = *(const float4*)(W + (size_t)(kc * BK + r) * N + col0 + c4);
            *(float4*)(stage + r * 132 + c4) = v;
        }
        __syncthreads();

        // ---- transpose+convert stage -> B tiles [n][k] hi/lo ----
        {
            const int n = tid & 127;
            const int kg = (tid >> 7) * 16;
            uint32_t hi[8], lo[8];
#pragma unroll
            for (int j = 0; j < 8; j++) {
                float f0 = stage[(kg + 2 * j) * 132 + n];
                float f1 = stage[(kg + 2 * j + 1) * 132 + n];
                cvt_pack(f0, f1, hi[j], lo[j]);
            }
            const uint32_t off = (uint32_t)n * (SA * 2) + (uint32_t)kg * 2;
            *(uint4*)(pBhi + off)      = make_uint4(hi[0], hi[1], hi[2], hi[3]);
            *(uint4*)(pBhi + off + 16) = make_uint4(hi[4], hi[5], hi[6], hi[7]);
            *(uint4*)(pBlo + off)      = make_uint4(lo[0], lo[1], lo[2], lo[3]);
            *(uint4*)(pBlo + off + 16) = make_uint4(lo[4], lo[5], lo[6], lo[7]);
        }
        __syncthreads();

        // ---- compute: 2 k16-steps ----
#pragma unroll
        for (int ks = 0; ks < 2; ks++) {
            const uint32_t kb = (uint32_t)ks * 32;  // byte offset of k-step
            // B fragments: 4 n-tiles (two x4 loads per hi/lo)
            uint32_t bh[4][2], bl[4][2];
#pragma unroll
            for (int ntp = 0; ntp < 2; ntp++) {
                const uint32_t boff = (uint32_t)(wn * 32 + ntp * 16) * (SA * 2) + kb + fragoff;
                uint32_t m[4];
                ldmx4(m, uBhi + boff);
                bh[ntp * 2 + 0][0] = m[0]; bh[ntp * 2 + 1][0] = m[1];
                bh[ntp * 2 + 0][1] = m[2]; bh[ntp * 2 + 1][1] = m[3];
                ldmx4(m, uBlo + boff);
                bl[ntp * 2 + 0][0] = m[0]; bl[ntp * 2 + 1][0] = m[1];
                bl[ntp * 2 + 0][1] = m[2]; bl[ntp * 2 + 1][1] = m[3];
            }
#pragma unroll
            for (int mt = 0; mt < 4; mt++) {
                const uint32_t aoff = (uint32_t)(wm * 64 + mt * 16) * (SA * 2) + kb + fragoff;
                uint32_t ah[4], al[4];
                ldmx4(ah, uAhi + aoff);
                ldmx4(al, uAlo + aoff);
#pragma unroll
                for (int nt = 0; nt < 4; nt++) {
                    mma_bf16(acc[mt][nt], ah, bh[nt]);
                    mma_bf16(acc[mt][nt], ah, bl[nt]);
                    mma_bf16(acc[mt][nt], al, bh[nt]);
                }
            }
        }
    }

    // ---- epilogue: bias + store ----
#pragma unroll
    for (int mt = 0; mt < 4; mt++) {
        const int r = row0 + wm * 64 + mt * 16 + (lane >> 2);
#pragma unroll
        for (int nt = 0; nt < 4; nt++) {
            const int c = col0 + wn * 32 + nt * 8 + (lane & 3) * 2;
            const float bx = bias[c];
            const float by = bias[c + 1];
            float2 o0 = make_float2(acc[mt][nt][0] + bx, acc[mt][nt][1] + by);
            float2 o1 = make_float2(acc[mt][nt][2] + bx, acc[mt][nt][3] + by);
            *(float2*)(C + (size_t)r * N + c) = o0;
            *(float2*)(C + (size_t)(r + 8) * N + c) = o1;
        }
    }
}

// ---------------------------------------------------------------------------
// Flash attention (unchanged from R1; no 1/sqrt(dk) scaling per reference).
// ---------------------------------------------------------------------------
__global__ void __launch_bounds__(256) flash_attn(
    const float* __restrict__ qkv, float* __restrict__ out)
{
    extern __shared__ float sm[];
    float* Qt = sm;            // [d][r]
    float* Kt = sm + 4096;     // [d][c]
    float* Vs = sm + 8192;     // [c][d]
    float* Ps = sm + 12288;    // [r][c]

    const int tid = threadIdx.x;
    const int tx = tid & 15;
    const int ty = tid >> 4;
    const int qt = blockIdx.x;
    const int bh = blockIdx.y;
    const int b = bh >> 4;
    const int h = bh & 15;
    const int R = ty * 4;
    const int Cc = tx * 4;

    const size_t ROW = 3 * Dd;
    const float* base = qkv + (size_t)b * Ss * ROW + h * DHd;

    {
        const int r = tid >> 2;
        const int quad = tid & 3;
        const float* qrow = base + (size_t)(qt * 64 + r) * ROW;
#pragma unroll
        for (int u = 0; u < 4; u++) {
            const int d0 = quad * 16 + u * 4;
            float4 v = *(const float4*)(qrow + d0);
            Qt[(d0 + 0) * 64 + r] = v.x;
            Qt[(d0 + 1) * 64 + r] = v.y;
            Qt[(d0 + 2) * 64 + r] = v.z;
            Qt[(d0 + 3) * 64 + r] = v.w;
        }
    }

    float oacc[4][4];
    float m[4], l[4];
#pragma unroll
    for (int i = 0; i < 4; i++) {
        m[i] = -1e30f;
        l[i] = 0.f;
#pragma unroll
        for (int j = 0; j < 4; j++) oacc[i][j] = 0.f;
    }

    for (int kt = 0; kt < Ss / 64; kt++) {
        __syncthreads();
        {
            const int r = tid >> 2;
            const int quad = tid & 3;
            const float* krow = base + (size_t)(kt * 64 + r) * ROW + Dd;
            const float* vrow = base + (size_t)(kt * 64 + r) * ROW + 2 * Dd;
#pragma unroll
            for (int u = 0; u < 4; u++) {
                const int d0 = quad * 16 + u * 4;
                float4 kv = *(const float4*)(krow + d0);
                Kt[(d0 + 0) * 64 + r] = kv.x;
                Kt[(d0 + 1) * 64 + r] = kv.y;
                Kt[(d0 + 2) * 64 + r] = kv.z;
                Kt[(d0 + 3) * 64 + r] = kv.w;
                *(float4*)&Vs[r * 64 + d0] = *(const float4*)(vrow + d0);
            }
        }
        __syncthreads();

        float s[4][4];
#pragma unroll
        for (int i = 0; i < 4; i++)
#pragma unroll
            for (int j = 0; j < 4; j++) s[i][j] = 0.f;

#pragma unroll 4
        for (int d = 0; d < 64; d++) {
            float4 q = *(const float4*)&Qt[d * 64 + R];
            float4 k = *(const float4*)&Kt[d * 64 + Cc];
            float qa[4] = {q.x, q.y, q.z, q.w};
            float ka[4] = {k.x, k.y, k.z, k.w};
#pragma unroll
            for (int i = 0; i < 4; i++)
#pragma unroll
                for (int j = 0; j < 4; j++)
                    s[i][j] = fmaf(qa[i], ka[j], s[i][j]);
        }

#pragma unroll
        for (int i = 0; i < 4; i++) {
            float mx = fmaxf(fmaxf(s[i][0], s[i][1]), fmaxf(s[i][2], s[i][3]));
#pragma unroll
            for (int off = 8; off > 0; off >>= 1)
                mx = fmaxf(mx, __shfl_xor_sync(0xffffffffu, mx, off));
            const float mnew = fmaxf(m[i], mx);
            const float corr = __expf(m[i] - mnew);
            float p0 = __expf(s[i][0] - mnew);
            float p1 = __expf(s[i][1] - mnew);
            float p2 = __expf(s[i][2] - mnew);
            float p3 = __expf(s[i][3] - mnew);
            float rs = p0 + p1 + p2 + p3;
#pragma unroll
            for (int off = 8; off > 0; off >>= 1)
                rs += __shfl_xor_sync(0xffffffffu, rs, off);
            l[i] = l[i] * corr + rs;
            m[i] = mnew;
#pragma unroll
            for (int j = 0; j < 4; j++) oacc[i][j] *= corr;
            *(float4*)&Ps[(R + i) * 64 + Cc] = make_float4(p0, p1, p2, p3);
        }
        __syncwarp();

#pragma unroll 4
        for (int c = 0; c < 64; c++) {
            float4 v = *(const float4*)&Vs[c * 64 + Cc];
            float va[4] = {v.x, v.y, v.z, v.w};
            float pr[4];
#pragma unroll
            for (int i = 0; i < 4; i++) pr[i] = Ps[(R + i) * 64 + c];
#pragma unroll
            for (int i = 0; i < 4; i++)
#pragma unroll
                for (int j = 0; j < 4; j++)
                    oacc[i][j] = fmaf(pr[i], va[j], oacc[i][j]);
        }
    }

#pragma unroll
    for (int i = 0; i < 4; i++) {
        const float inv = 1.f / l[i];
        float4 o;
        o.x = oacc[i][0] * inv;
        o.y = oacc[i][1] * inv;
        o.z = oacc[i][2] * inv;
        o.w = oacc[i][3] * inv;
        const size_t orow = ((size_t)b * Ss + qt * 64 + R + i) * Dd + h * DHd + Cc;
        *(float4*)(out + orow) = o;
    }
}

// ---------------------------------------------------------------------------
extern "C" void kernel_launch(void* const* d_in, const int* in_sizes, int n_in,
                              void* d_out, int out_size)
{
    (void)in_sizes; (void)n_in; (void)out_size;
    const float* x  = (const float*)d_in[0];
    const float* w1 = (const float*)d_in[1];
    const float* b1 = (const float*)d_in[2];
    const float* w2 = (const float*)d_in[3];
    const float* b2 = (const float*)d_in[4];
    float* out = (float*)d_out;

    float* qkv;  cudaGetSymbolAddress((void**)&qkv,  g_qkv);
    float* attn; cudaGetSymbolAddress((void**)&attn, g_attn);

    cudaFuncSetAttribute(gemm_mma, cudaFuncAttributeMaxDynamicSharedMemorySize, GEMM_SMEM);
    cudaFuncSetAttribute(flash_attn, cudaFuncAttributeMaxDynamicSharedMemorySize, 65536);

    const int M = Bb * Ss;  // 8192
    // 1) QKV projection: [8192,1024] @ [1024,3072] + b1
    gemm_mma<<<dim3(3 * Dd / 128, M / 128), 256, GEMM_SMEM>>>(x, w1, b1, qkv, M, 3 * Dd, Dd);
    // 2) Attention
    flash_attn<<<dim3(Ss / 64, Bb * Hh), 256, 65536>>>(qkv, attn);
    // 3) Output projection: [8192,1024] @ [1024,1024] + b2
    gemm_mma<<<dim3(Dd / 128, M / 128), 256, GEMM_SMEM>>>(attn, w2, b2, out, M, Dd, Dd);
}

// round 4
// speedup vs baseline: 2.1804x; 1.7039x over previous
#include <cuda_runtime.h>
#include <cuda_bf16.h>
#include <cstdint>

// Problem constants
#define Bb 4
#define Ss 2048
#define Dd 1024
#define Hh 16
#define DHd 64

// Scratch
__device__ float g_qkv[(size_t)Bb * Ss * 3 * Dd];   // [8192, 3072]
__device__ float g_attn[(size_t)Bb * Ss * Dd];      // [8192, 1024]

// ---------------------------------------------------------------------------
// Helpers (portable: ldmatrix sm_75+, mma.sync bf16 sm_80+)
// ---------------------------------------------------------------------------
__device__ __forceinline__ uint32_t s2u(const void* p) {
    uint32_t a;
    asm("{ .reg .u64 t; cvta.to.shared.u64 t, %1; cvt.u32.u64 %0, t; }" : "=r"(a) : "l"(p));
    return a;
}

__device__ __forceinline__ void ldmx4(uint32_t* r, uint32_t addr) {
    asm volatile("ldmatrix.sync.aligned.m8n8.x4.shared.b16 {%0,%1,%2,%3}, [%4];"
        : "=r"(r[0]), "=r"(r[1]), "=r"(r[2]), "=r"(r[3]) : "r"(addr));
}

__device__ __forceinline__ void mma_bf16(float* c, const uint32_t* a, const uint32_t* b) {
    asm volatile("mma.sync.aligned.m16n8k16.row.col.f32.bf16.bf16.f32 "
        "{%0,%1,%2,%3}, {%4,%5,%6,%7}, {%8,%9}, {%0,%1,%2,%3};"
        : "+f"(c[0]), "+f"(c[1]), "+f"(c[2]), "+f"(c[3])
        : "r"(a[0]), "r"(a[1]), "r"(a[2]), "r"(a[3]), "r"(b[0]), "r"(b[1]));
}

// fp32 pair -> packed hi bf16x2 and lo bf16x2 (hi = rn(f), lo = rn(f - hi))
__device__ __forceinline__ void cvt_pack(float f0, float f1, uint32_t& hi, uint32_t& lo) {
    __nv_bfloat16 h0 = __float2bfloat16(f0);
    __nv_bfloat16 h1 = __float2bfloat16(f1);
    __nv_bfloat16 l0 = __float2bfloat16(f0 - __bfloat162float(h0));
    __nv_bfloat16 l1 = __float2bfloat16(f1 - __bfloat162float(h1));
    hi = ((uint32_t)__bfloat16_as_ushort(h1) << 16) | (uint32_t)__bfloat16_as_ushort(h0);
    lo = ((uint32_t)__bfloat16_as_ushort(l1) << 16) | (uint32_t)__bfloat16_as_ushort(l0);
}

// ---------------------------------------------------------------------------
// Tensor-core GEMM via mma.sync (unchanged from R3).
// ---------------------------------------------------------------------------
#define BK 32
#define SA 40
#define TILE_B (128 * SA * 2)
#define OFF_AHI 0
#define OFF_ALO (TILE_B)
#define OFF_BHI (2 * TILE_B)
#define OFF_BLO (3 * TILE_B)
#define OFF_STG (4 * TILE_B)
#define GEMM_SMEM (OFF_STG + BK * 132 * 4)

__global__ void __launch_bounds__(256, 2) gemm_mma(
    const float* __restrict__ A, const float* __restrict__ W,
    const float* __restrict__ bias, float* __restrict__ C,
    int M, int N, int K)
{
    extern __shared__ char smem[];
    char* pAhi = smem + OFF_AHI;
    char* pAlo = smem + OFF_ALO;
    char* pBhi = smem + OFF_BHI;
    char* pBlo = smem + OFF_BLO;
    float* stage = (float*)(smem + OFF_STG);

    const int tid = threadIdx.x;
    const int lane = tid & 31;
    const int warp = tid >> 5;
    const int wm = warp >> 2;
    const int wn = warp & 3;
    const int row0 = blockIdx.y * 128;
    const int col0 = blockIdx.x * 128;

    const uint32_t uAhi = s2u(pAhi);
    const uint32_t uAlo = s2u(pAlo);
    const uint32_t uBhi = s2u(pBhi);
    const uint32_t uBlo = s2u(pBlo);

    float acc[4][4][4];
#pragma unroll
    for (int i = 0; i < 4; i++)
#pragma unroll
        for (int j = 0; j < 4; j++)
#pragma unroll
            for (int e = 0; e < 4; e++) acc[i][j][e] = 0.f;

    const uint32_t fragoff = (uint32_t)(lane & 15) * (SA * 2) + (uint32_t)(lane >> 4) * 16;

    const int nchunks = K / BK;
    for (int kc = 0; kc < nchunks; kc++) {
        __syncthreads();
        {
            const int r = tid >> 1;
            const int kh = (tid & 1) * 16;
            const float* src = A + (size_t)(row0 + r) * K + kc * BK + kh;
            float4 v0 = *(const float4*)(src + 0);
            float4 v1 = *(const float4*)(src + 4);
            float4 v2 = *(const float4*)(src + 8);
            float4 v3 = *(const float4*)(src + 12);
            uint32_t hi[8], lo[8];
            cvt_pack(v0.x, v0.y, hi[0], lo[0]);
            cvt_pack(v0.z, v0.w, hi[1], lo[1]);
            cvt_pack(v1.x, v1.y, hi[2], lo[2]);
            cvt_pack(v1.z, v1.w, hi[3], lo[3]);
            cvt_pack(v2.x, v2.y, hi[4], lo[4]);
            cvt_pack(v2.z, v2.w, hi[5], lo[5]);
            cvt_pack(v3.x, v3.y, hi[6], lo[6]);
            cvt_pack(v3.z, v3.w, hi[7], lo[7]);
            const uint32_t off = (uint32_t)r * (SA * 2) + (uint32_t)kh * 2;
            *(uint4*)(pAhi + off)      = make_uint4(hi[0], hi[1], hi[2], hi[3]);
            *(uint4*)(pAhi + off + 16) = make_uint4(hi[4], hi[5], hi[6], hi[7]);
            *(uint4*)(pAlo + off)      = make_uint4(lo[0], lo[1], lo[2], lo[3]);
            *(uint4*)(pAlo + off + 16) = make_uint4(lo[4], lo[5], lo[6], lo[7]);
        }
#pragma unroll
        for (int u = 0; u < 4; u++) {
            const int id = u * 256 + tid;
            const int r = id >> 5;
            const int c4 = (id & 31) * 4;
            float4 v = *(const float4*)(W + (size_t)(kc * BK + r) * N + col0 + c4);
            *(float4*)(stage + r * 132 + c4) = v;
        }
        __syncthreads();
        {
            const int n = tid & 127;
            const int kg = (tid >> 7) * 16;
            uint32_t hi[8], lo[8];
#pragma unroll
            for (int j = 0; j < 8; j++) {
                float f0 = stage[(kg + 2 * j) * 132 + n];
                float f1 = stage[(kg + 2 * j + 1) * 132 + n];
                cvt_pack(f0, f1, hi[j], lo[j]);
            }
            const uint32_t off = (uint32_t)n * (SA * 2) + (uint32_t)kg * 2;
            *(uint4*)(pBhi + off)      = make_uint4(hi[0], hi[1], hi[2], hi[3]);
            *(uint4*)(pBhi + off + 16) = make_uint4(hi[4], hi[5], hi[6], hi[7]);
            *(uint4*)(pBlo + off)      = make_uint4(lo[0], lo[1], lo[2], lo[3]);
            *(uint4*)(pBlo + off + 16) = make_uint4(lo[4], lo[5], lo[6], lo[7]);
        }
        __syncthreads();

#pragma unroll
        for (int ks = 0; ks < 2; ks++) {
            const uint32_t kb = (uint32_t)ks * 32;
            uint32_t bh[4][2], bl[4][2];
#pragma unroll
            for (int ntp = 0; ntp < 2; ntp++) {
                const uint32_t boff = (uint32_t)(wn * 32 + ntp * 16) * (SA * 2) + kb + fragoff;
                uint32_t m[4];
                ldmx4(m, uBhi + boff);
                bh[ntp * 2 + 0][0] = m[0]; bh[ntp * 2 + 1][0] = m[1];
                bh[ntp * 2 + 0][1] = m[2]; bh[ntp * 2 + 1][1] = m[3];
                ldmx4(m, uBlo + boff);
                bl[ntp * 2 + 0][0] = m[0]; bl[ntp * 2 + 1][0] = m[1];
                bl[ntp * 2 + 0][1] = m[2]; bl[ntp * 2 + 1][1] = m[3];
            }
#pragma unroll
            for (int mt = 0; mt < 4; mt++) {
                const uint32_t aoff = (uint32_t)(wm * 64 + mt * 16) * (SA * 2) + kb + fragoff;
                uint32_t ah[4], al[4];
                ldmx4(ah, uAhi + aoff);
                ldmx4(al, uAlo + aoff);
#pragma unroll
                for (int nt = 0; nt < 4; nt++) {
                    mma_bf16(acc[mt][nt], ah, bh[nt]);
                    mma_bf16(acc[mt][nt], ah, bl[nt]);
                    mma_bf16(acc[mt][nt], al, bh[nt]);
                }
            }
        }
    }

#pragma unroll
    for (int mt = 0; mt < 4; mt++) {
        const int r = row0 + wm * 64 + mt * 16 + (lane >> 2);
#pragma unroll
        for (int nt = 0; nt < 4; nt++) {
            const int c = col0 + wn * 32 + nt * 8 + (lane & 3) * 2;
            const float bx = bias[c];
            const float by = bias[c + 1];
            float2 o0 = make_float2(acc[mt][nt][0] + bx, acc[mt][nt][1] + by);
            float2 o1 = make_float2(acc[mt][nt][2] + bx, acc[mt][nt][3] + by);
            *(float2*)(C + (size_t)r * N + c) = o0;
            *(float2*)(C + (size_t)(r + 8) * N + c) = o1;
        }
    }
}

// ---------------------------------------------------------------------------
// Tensor-core flash attention. CTA = 128 queries x one (b,h). 8 warps x 16 rows.
// bf16 hi/lo split for QK and PV (3 MMAs each). S/P stay in registers.
// K/V double-buffered in smem with register-staged prefetch.
// ---------------------------------------------------------------------------
#define KS 72                      // padded bf16 row stride (144 B = 9x16B banks)
#define ROWB (KS * 2)              // 144
#define ATILE (64 * ROWB)          // 9216 B per 64x64 bf16 tile
#define STAGE_B (4 * ATILE)        // Khi,Klo,Vthi,Vtlo = 36864
#define ATTN_SMEM (2 * STAGE_B)    // 73728

__global__ void __launch_bounds__(256) flash_mma(
    const float* __restrict__ qkv, float* __restrict__ out)
{
    extern __shared__ char smem[];
    const int tid = threadIdx.x;
    const int lane = tid & 31;
    const int warp = tid >> 5;
    const int qt = blockIdx.x;     // 0..15 (128-query tiles)
    const int bh = blockIdx.y;     // 0..63
    const int b = bh >> 4;
    const int h = bh & 15;

    const size_t ROW = 3 * Dd;
    const float* qbase = qkv + (size_t)b * Ss * ROW + h * DHd;          // Q
    const float* kbase = qbase + Dd;                                     // K
    const float* vbase = qbase + 2 * Dd;                                 // V

    const uint32_t sb = s2u(smem);
    const uint32_t fragoff = (uint32_t)(lane & 15) * ROWB + (uint32_t)(lane >> 4) * 16;

    // ---------------- prefetch K/V block 0 into registers ----------------
    float kf[16], vf[16];
    const int kr = tid >> 2;              // key row for K load (0..63)
    const int kq = (tid & 3) * 16;        // dh quarter
    const int vr = tid & 63;              // key row for V load
    const int vc = (tid >> 6) * 16;       // dh chunk
    {
        const float* ks_ = kbase + (size_t)kr * ROW + kq;
        const float* vs_ = vbase + (size_t)vr * ROW + vc;
#pragma unroll
        for (int i = 0; i < 4; i++) {
            *(float4*)(kf + i * 4) = *(const float4*)(ks_ + i * 4);
            *(float4*)(vf + i * 4) = *(const float4*)(vs_ + i * 4);
        }
    }

    // ---------------- Q phase: stage to smem, ldmatrix to regs ----------------
    uint32_t qh[4][4], ql[4][4];
    {
        char* Qhi = smem;                 // 128 x KS bf16
        char* Qlo = smem + 128 * ROWB;
        const int r = tid >> 1;
        const int half = (tid & 1) * 32;
        const float* src = qbase + (size_t)(qt * 128 + r) * ROW + half;
        uint32_t hi[16], lo[16];
#pragma unroll
        for (int i = 0; i < 8; i++) {
            float4 v = *(const float4*)(src + i * 4);
            cvt_pack(v.x, v.y, hi[i * 2], lo[i * 2]);
            cvt_pack(v.z, v.w, hi[i * 2 + 1], lo[i * 2 + 1]);
        }
        const uint32_t off = (uint32_t)r * ROWB + (uint32_t)half * 2;
#pragma unroll
        for (int i = 0; i < 4; i++) {
            *(uint4*)(Qhi + off + i * 16) = *(uint4*)(hi + i * 4);
            *(uint4*)(Qlo + off + i * 16) = *(uint4*)(lo + i * 4);
        }
        __syncthreads();
        const uint32_t uQhi = sb;
        const uint32_t uQlo = sb + 128 * ROWB;
#pragma unroll
        for (int j = 0; j < 4; j++) {
            const uint32_t aoff = (uint32_t)(warp * 16) * ROWB + j * 32 + fragoff;
            ldmx4(qh[j], uQhi + aoff);
            ldmx4(ql[j], uQlo + aoff);
        }
        __syncthreads();
    }

    // ---------------- accumulators ----------------
    float o[8][4];
    float m0 = -1e30f, m1 = -1e30f, l0 = 0.f, l1 = 0.f;
#pragma unroll
    for (int i = 0; i < 8; i++)
#pragma unroll
        for (int e = 0; e < 4; e++) o[i][e] = 0.f;

    // ---------------- key-block loop ----------------
    for (int kb = 0; kb < Ss / 64; kb++) {
        const int s = kb & 1;
        char* stg = smem + s * STAGE_B;
        char* Khi = stg;
        char* Klo = stg + ATILE;
        char* Vthi = stg + 2 * ATILE;
        char* Vtlo = stg + 3 * ATILE;

        __syncthreads();   // buffer s free (all warps finished block kb-2)

        // STS: K natural [key][dh], V transposed [dh][key]
        {
            uint32_t hi[8], lo[8];
#pragma unroll
            for (int i = 0; i < 8; i++) cvt_pack(kf[i * 2], kf[i * 2 + 1], hi[i], lo[i]);
            const uint32_t off = (uint32_t)kr * ROWB + (uint32_t)kq * 2;
            *(uint4*)(Khi + off)      = *(uint4*)(hi + 0);
            *(uint4*)(Khi + off + 16) = *(uint4*)(hi + 4);
            *(uint4*)(Klo + off)      = *(uint4*)(lo + 0);
            *(uint4*)(Klo + off + 16) = *(uint4*)(lo + 4);
#pragma unroll
            for (int i = 0; i < 16; i++) {
                const float f = vf[i];
                const __nv_bfloat16 hb = __float2bfloat16(f);
                const __nv_bfloat16 lb = __float2bfloat16(f - __bfloat162float(hb));
                const uint32_t voff = (uint32_t)(vc + i) * ROWB + (uint32_t)vr * 2;
                *(__nv_bfloat16*)(Vthi + voff) = hb;
                *(__nv_bfloat16*)(Vtlo + voff) = lb;
            }
        }
        __syncthreads();

        // prefetch next block
        if (kb + 1 < Ss / 64) {
            const float* ks_ = kbase + (size_t)((kb + 1) * 64 + kr) * ROW + kq;
            const float* vs_ = vbase + (size_t)((kb + 1) * 64 + vr) * ROW + vc;
#pragma unroll
            for (int i = 0; i < 4; i++) {
                *(float4*)(kf + i * 4) = *(const float4*)(ks_ + i * 4);
                *(float4*)(vf + i * 4) = *(const float4*)(vs_ + i * 4);
            }
        }

        const uint32_t uKhi = s2u(Khi);
        const uint32_t uKlo = s2u(Klo);
        const uint32_t uVthi = s2u(Vthi);
        const uint32_t uVtlo = s2u(Vtlo);

        // ---- S = Q K^T ----
        float sc[8][4];
#pragma unroll
        for (int i = 0; i < 8; i++)
#pragma unroll
            for (int e = 0; e < 4; e++) sc[i][e] = 0.f;

#pragma unroll
        for (int g = 0; g < 4; g++) {
#pragma unroll
            for (int j = 0; j < 4; j++) {
                const uint32_t boff = (uint32_t)(g * 16) * ROWB + j * 32 + fragoff;
                uint32_t mh[4], ml[4];
                ldmx4(mh, uKhi + boff);
                ldmx4(ml, uKlo + boff);
                uint32_t b0h[2] = {mh[0], mh[2]}, b1h[2] = {mh[1], mh[3]};
                uint32_t b0l[2] = {ml[0], ml[2]}, b1l[2] = {ml[1], ml[3]};
                mma_bf16(sc[2 * g + 0], qh[j], b0h);
                mma_bf16(sc[2 * g + 0], qh[j], b0l);
                mma_bf16(sc[2 * g + 0], ql[j], b0h);
                mma_bf16(sc[2 * g + 1], qh[j], b1h);
                mma_bf16(sc[2 * g + 1], qh[j], b1l);
                mma_bf16(sc[2 * g + 1], ql[j], b1h);
            }
        }

        // ---- online softmax ----
        float mx0 = -1e30f, mx1 = -1e30f;
#pragma unroll
        for (int i = 0; i < 8; i++) {
            mx0 = fmaxf(mx0, fmaxf(sc[i][0], sc[i][1]));
            mx1 = fmaxf(mx1, fmaxf(sc[i][2], sc[i][3]));
        }
        mx0 = fmaxf(mx0, __shfl_xor_sync(0xffffffffu, mx0, 1));
        mx0 = fmaxf(mx0, __shfl_xor_sync(0xffffffffu, mx0, 2));
        mx1 = fmaxf(mx1, __shfl_xor_sync(0xffffffffu, mx1, 1));
        mx1 = fmaxf(mx1, __shfl_xor_sync(0xffffffffu, mx1, 2));
        const float mn0 = fmaxf(m0, mx0);
        const float mn1 = fmaxf(m1, mx1);
        const float c0 = __expf(m0 - mn0);
        const float c1 = __expf(m1 - mn1);
        float rs0 = 0.f, rs1 = 0.f;
#pragma unroll
        for (int i = 0; i < 8; i++) {
            sc[i][0] = __expf(sc[i][0] - mn0);
            sc[i][1] = __expf(sc[i][1] - mn0);
            sc[i][2] = __expf(sc[i][2] - mn1);
            sc[i][3] = __expf(sc[i][3] - mn1);
            rs0 += sc[i][0] + sc[i][1];
            rs1 += sc[i][2] + sc[i][3];
        }
        rs0 += __shfl_xor_sync(0xffffffffu, rs0, 1);
        rs0 += __shfl_xor_sync(0xffffffffu, rs0, 2);
        rs1 += __shfl_xor_sync(0xffffffffu, rs1, 1);
        rs1 += __shfl_xor_sync(0xffffffffu, rs1, 2);
        l0 = l0 * c0 + rs0;
        l1 = l1 * c1 + rs1;
        m0 = mn0;
        m1 = mn1;
#pragma unroll
        for (int i = 0; i < 8; i++) {
            o[i][0] *= c0; o[i][1] *= c0;
            o[i][2] *= c1; o[i][3] *= c1;
        }

        // ---- repack P (C-frag -> A-frag), hi/lo ----
        uint32_t ph[4][4], pl[4][4];
#pragma unroll
        for (int j = 0; j < 4; j++) {
            cvt_pack(sc[2 * j][0],     sc[2 * j][1],     ph[j][0], pl[j][0]);
            cvt_pack(sc[2 * j][2],     sc[2 * j][3],     ph[j][1], pl[j][1]);
            cvt_pack(sc[2 * j + 1][0], sc[2 * j + 1][1], ph[j][2], pl[j][2]);
            cvt_pack(sc[2 * j + 1][2], sc[2 * j + 1][3], ph[j][3], pl[j][3]);
        }

        // ---- O += P V ----
#pragma unroll
        for (int g = 0; g < 4; g++) {
#pragma unroll
            for (int j = 0; j < 4; j++) {
                const uint32_t boff = (uint32_t)(g * 16) * ROWB + j * 32 + fragoff;
                uint32_t mh[4], ml[4];
                ldmx4(mh, uVthi + boff);
                ldmx4(ml, uVtlo + boff);
                uint32_t b0h[2] = {mh[0], mh[2]}, b1h[2] = {mh[1], mh[3]};
                uint32_t b0l[2] = {ml[0], ml[2]}, b1l[2] = {ml[1], ml[3]};
                mma_bf16(o[2 * g + 0], ph[j], b0h);
                mma_bf16(o[2 * g + 0], ph[j], b0l);
                mma_bf16(o[2 * g + 0], pl[j], b0h);
                mma_bf16(o[2 * g + 1], ph[j], b1h);
                mma_bf16(o[2 * g + 1], ph[j], b1l);
                mma_bf16(o[2 * g + 1], pl[j], b1h);
            }
        }
    }

    // ---------------- epilogue ----------------
    const float inv0 = 1.f / l0;
    const float inv1 = 1.f / l1;
    const int r0 = qt * 128 + warp * 16 + (lane >> 2);
    const size_t obase = ((size_t)b * Ss + r0) * Dd + h * DHd + (lane & 3) * 2;
#pragma unroll
    for (int nt = 0; nt < 8; nt++) {
        float2 v0 = make_float2(o[nt][0] * inv0, o[nt][1] * inv0);
        float2 v1 = make_float2(o[nt][2] * inv1, o[nt][3] * inv1);
        *(float2*)(out + obase + nt * 8) = v0;
        *(float2*)(out + obase + (size_t)8 * Dd + nt * 8) = v1;
    }
}

// ---------------------------------------------------------------------------
extern "C" void kernel_launch(void* const* d_in, const int* in_sizes, int n_in,
                              void* d_out, int out_size)
{
    (void)in_sizes; (void)n_in; (void)out_size;
    const float* x  = (const float*)d_in[0];
    const float* w1 = (const float*)d_in[1];
    const float* b1 = (const float*)d_in[2];
    const float* w2 = (const float*)d_in[3];
    const float* b2 = (const float*)d_in[4];
    float* out = (float*)d_out;

    float* qkv;  cudaGetSymbolAddress((void**)&qkv,  g_qkv);
    float* attn; cudaGetSymbolAddress((void**)&attn, g_attn);

    cudaFuncSetAttribute(gemm_mma, cudaFuncAttributeMaxDynamicSharedMemorySize, GEMM_SMEM);
    cudaFuncSetAttribute(flash_mma, cudaFuncAttributeMaxDynamicSharedMemorySize, ATTN_SMEM);

    const int M = Bb * Ss;  // 8192
    gemm_mma<<<dim3(3 * Dd / 128, M / 128), 256, GEMM_SMEM>>>(x, w1, b1, qkv, M, 3 * Dd, Dd);
    flash_mma<<<dim3(Ss / 128, Bb * Hh), 256, ATTN_SMEM>>>(qkv, attn);
    gemm_mma<<<dim3(Dd / 128, M / 128), 256, GEMM_SMEM>>>(attn, w2, b2, out, M, Dd, Dd);
}

// round 5
// speedup vs baseline: 2.5873x; 1.1866x over previous
#include <cuda_runtime.h>
#include <cuda_bf16.h>
#include <cstdint>

// Problem constants
#define Bb 4
#define Ss 2048
#define Dd 1024
#define Hh 16
#define DHd 64
#define MM (Bb * Ss)          // 8192
#define N1 (3 * Dd)           // 3072

// ---------------- global scratch (bf16 hi/lo planes) ----------------
__device__ __nv_bfloat16 g_xhi[(size_t)MM * Dd];
__device__ __nv_bfloat16 g_xlo[(size_t)MM * Dd];
__device__ __nv_bfloat16 g_w1hi[(size_t)N1 * Dd];    // [n][k]
__device__ __nv_bfloat16 g_w1lo[(size_t)N1 * Dd];
__device__ __nv_bfloat16 g_w2hi[(size_t)Dd * Dd];    // [n][k]
__device__ __nv_bfloat16 g_w2lo[(size_t)Dd * Dd];
__device__ __nv_bfloat16 g_qkvhi[(size_t)MM * N1];
__device__ __nv_bfloat16 g_qkvlo[(size_t)MM * N1];
__device__ __nv_bfloat16 g_ahi[(size_t)MM * Dd];
__device__ __nv_bfloat16 g_alo[(size_t)MM * Dd];

// ---------------- helpers ----------------
__device__ __forceinline__ uint32_t s2u(const void* p) {
    uint32_t a;
    asm("{ .reg .u64 t; cvta.to.shared.u64 t, %1; cvt.u32.u64 %0, t; }" : "=r"(a) : "l"(p));
    return a;
}
__device__ __forceinline__ void cp16(uint32_t saddr, const void* gaddr) {
    asm volatile("cp.async.cg.shared.global [%0], [%1], 16;" :: "r"(saddr), "l"(gaddr));
}
#define CP_COMMIT() asm volatile("cp.async.commit_group;" ::: "memory")
#define CP_WAIT0()  asm volatile("cp.async.wait_group 0;" ::: "memory")

__device__ __forceinline__ void ldmx4(uint32_t* r, uint32_t addr) {
    asm volatile("ldmatrix.sync.aligned.m8n8.x4.shared.b16 {%0,%1,%2,%3}, [%4];"
        : "=r"(r[0]), "=r"(r[1]), "=r"(r[2]), "=r"(r[3]) : "r"(addr));
}
__device__ __forceinline__ void ldmx4t(uint32_t* r, uint32_t addr) {
    asm volatile("ldmatrix.sync.aligned.m8n8.x4.trans.shared.b16 {%0,%1,%2,%3}, [%4];"
        : "=r"(r[0]), "=r"(r[1]), "=r"(r[2]), "=r"(r[3]) : "r"(addr));
}
__device__ __forceinline__ void mma_bf16(float* c, const uint32_t* a, const uint32_t* b) {
    asm volatile("mma.sync.aligned.m16n8k16.row.col.f32.bf16.bf16.f32 "
        "{%0,%1,%2,%3}, {%4,%5,%6,%7}, {%8,%9}, {%0,%1,%2,%3};"
        : "+f"(c[0]), "+f"(c[1]), "+f"(c[2]), "+f"(c[3])
        : "r"(a[0]), "r"(a[1]), "r"(a[2]), "r"(a[3]), "r"(b[0]), "r"(b[1]));
}
__device__ __forceinline__ void cvt_pack(float f0, float f1, uint32_t& hi, uint32_t& lo) {
    __nv_bfloat16 h0 = __float2bfloat16(f0);
    __nv_bfloat16 h1 = __float2bfloat16(f1);
    __nv_bfloat16 l0 = __float2bfloat16(f0 - __bfloat162float(h0));
    __nv_bfloat16 l1 = __float2bfloat16(f1 - __bfloat162float(h1));
    hi = ((uint32_t)__bfloat16_as_ushort(h1) << 16) | (uint32_t)__bfloat16_as_ushort(h0);
    lo = ((uint32_t)__bfloat16_as_ushort(l1) << 16) | (uint32_t)__bfloat16_as_ushort(l0);
}

// ---------------- pre-convert kernels ----------------
__global__ void __launch_bounds__(256) split_f32(
    const float* __restrict__ src, __nv_bfloat16* __restrict__ hi,
    __nv_bfloat16* __restrict__ lo, int n2)  // n2 = elems/2
{
    int i = blockIdx.x * 256 + threadIdx.x;
    if (i >= n2) return;
    float2 v = *(const float2*)(src + 2 * i);
    uint32_t h, l;
    cvt_pack(v.x, v.y, h, l);
    ((uint32_t*)hi)[i] = h;
    ((uint32_t*)lo)[i] = l;
}

// W[K][N] fp32 -> Wt hi/lo [N][K] bf16
__global__ void __launch_bounds__(256) transpose_split(
    const float* __restrict__ W, __nv_bfloat16* __restrict__ Whi,
    __nv_bfloat16* __restrict__ Wlo, int K, int N)
{
    __shared__ float sm[64][33];
    const int tid = threadIdx.x;
    const int n0 = blockIdx.x * 32;
    const int k0 = blockIdx.y * 64;
#pragma unroll
    for (int p = 0; p < 8; p++) {
        const int k = p * 8 + (tid >> 5);
        const int n = tid & 31;
        sm[k][n] = W[(size_t)(k0 + k) * N + n0 + n];
    }
    __syncthreads();
#pragma unroll
    for (int p = 0; p < 4; p++) {
        const int n = p * 8 + (tid >> 5);
        const int kp = tid & 31;
        uint32_t h, l;
        cvt_pack(sm[2 * kp][n], sm[2 * kp + 1][n], h, l);
        const size_t idx = ((size_t)(n0 + n) * K + k0) / 2 + kp;
        ((uint32_t*)Whi)[idx] = h;
        ((uint32_t*)Wlo)[idx] = l;
    }
}

// ---------------------------------------------------------------------------
// GEMM from preconverted bf16 planes. C = A @ B^T(+bias), A [M][K], B [N][K].
// 128x128 tile, BK=32, cp.async double-buffered, 8 warps (2m x 4n).
// EPI: 0 -> fp32 C, 1 -> hi/lo bf16 planes.
// ---------------------------------------------------------------------------
#define GST 80                      // smem row stride bytes (32 bf16 + pad)
#define GTILE (128 * GST)           // 10240
#define GSTAGE (4 * GTILE)          // 40960
#define GEMM_SMEM (2 * GSTAGE)      // 81920

template<int EPI>
__global__ void __launch_bounds__(256, 2) gemm_bf(
    const __nv_bfloat16* __restrict__ Ahi, const __nv_bfloat16* __restrict__ Alo,
    const __nv_bfloat16* __restrict__ Bhi, const __nv_bfloat16* __restrict__ Blo,
    const float* __restrict__ bias, float* __restrict__ Cf,
    __nv_bfloat16* __restrict__ Chi, __nv_bfloat16* __restrict__ Clo,
    int M, int N, int K)
{
    extern __shared__ char smem[];
    const int tid = threadIdx.x;
    const int lane = tid & 31;
    const int warp = tid >> 5;
    const int wm = warp >> 2;
    const int wn = warp & 3;
    const int row0 = blockIdx.y * 128;
    const int col0 = blockIdx.x * 128;

    const int lrow = tid >> 1;          // 0..127
    const int lq = (tid & 1) * 2;       // chunk pair base

    auto issue = [&](int kc, int s) {
        char* stg = smem + s * GSTAGE;
        const uint32_t sA = s2u(stg) + (uint32_t)lrow * GST + lq * 16;
        const size_t gOffA = (size_t)(row0 + lrow) * K + kc * 32 + lq * 8;
        cp16(sA, Ahi + gOffA);
        cp16(sA + 16, Ahi + gOffA + 8);
        cp16(sA + GTILE, Alo + gOffA);
        cp16(sA + GTILE + 16, Alo + gOffA + 8);
        const size_t gOffB = (size_t)(col0 + lrow) * K + kc * 32 + lq * 8;
        cp16(sA + 2 * GTILE, Bhi + gOffB);
        cp16(sA + 2 * GTILE + 16, Bhi + gOffB + 8);
        cp16(sA + 3 * GTILE, Blo + gOffB);
        cp16(sA + 3 * GTILE + 16, Blo + gOffB + 8);
    };

    float acc[4][4][4];
#pragma unroll
    for (int i = 0; i < 4; i++)
#pragma unroll
        for (int j = 0; j < 4; j++)
#pragma unroll
            for (int e = 0; e < 4; e++) acc[i][j][e] = 0.f;

    const uint32_t fragoff = (uint32_t)(lane & 15) * GST + (uint32_t)(lane >> 4) * 16;

    issue(0, 0);
    CP_COMMIT();

    const int nch = K / 32;
    for (int kc = 0; kc < nch; kc++) {
        const int s = kc & 1;
        CP_WAIT0();
        __syncthreads();
        if (kc + 1 < nch) {
            issue(kc + 1, s ^ 1);
            CP_COMMIT();
        }
        char* stg = smem + s * GSTAGE;
        const uint32_t uAhi = s2u(stg);
        const uint32_t uAlo = uAhi + GTILE;
        const uint32_t uBhi = uAhi + 2 * GTILE;
        const uint32_t uBlo = uAhi + 3 * GTILE;

#pragma unroll
        for (int ks = 0; ks < 2; ks++) {
            const uint32_t kb = (uint32_t)ks * 32;
            uint32_t bh[4][2], bl[4][2];
#pragma unroll
            for (int ntp = 0; ntp < 2; ntp++) {
                const uint32_t boff = (uint32_t)(wn * 32 + ntp * 16) * GST + kb + fragoff;
                uint32_t m[4];
                ldmx4(m, uBhi + boff);
                bh[ntp * 2 + 0][0] = m[0]; bh[ntp * 2 + 1][0] = m[1];
                bh[ntp * 2 + 0][1] = m[2]; bh[ntp * 2 + 1][1] = m[3];
                ldmx4(m, uBlo + boff);
                bl[ntp * 2 + 0][0] = m[0]; bl[ntp * 2 + 1][0] = m[1];
                bl[ntp * 2 + 0][1] = m[2]; bl[ntp * 2 + 1][1] = m[3];
            }
#pragma unroll
            for (int mt = 0; mt < 4; mt++) {
                const uint32_t aoff = (uint32_t)(wm * 64 + mt * 16) * GST + kb + fragoff;
                uint32_t ah[4], al[4];
                ldmx4(ah, uAhi + aoff);
                ldmx4(al, uAlo + aoff);
#pragma unroll
                for (int nt = 0; nt < 4; nt++) {
                    mma_bf16(acc[mt][nt], ah, bh[nt]);
                    mma_bf16(acc[mt][nt], ah, bl[nt]);
                    mma_bf16(acc[mt][nt], al, bh[nt]);
                }
            }
        }
    }

    // epilogue
#pragma unroll
    for (int mt = 0; mt < 4; mt++) {
        const int r = row0 + wm * 64 + mt * 16 + (lane >> 2);
#pragma unroll
        for (int nt = 0; nt < 4; nt++) {
            const int c = col0 + wn * 32 + nt * 8 + (lane & 3) * 2;
            const float bx = bias[c];
            const float by = bias[c + 1];
            const float f0 = acc[mt][nt][0] + bx;
            const float f1 = acc[mt][nt][1] + by;
            const float f2 = acc[mt][nt][2] + bx;
            const float f3 = acc[mt][nt][3] + by;
            if (EPI == 0) {
                *(float2*)(Cf + (size_t)r * N + c) = make_float2(f0, f1);
                *(float2*)(Cf + (size_t)(r + 8) * N + c) = make_float2(f2, f3);
            } else {
                uint32_t h0, l0, h1, l1;
                cvt_pack(f0, f1, h0, l0);
                cvt_pack(f2, f3, h1, l1);
                const size_t i0 = ((size_t)r * N + c) / 2;
                const size_t i1 = ((size_t)(r + 8) * N + c) / 2;
                ((uint32_t*)Chi)[i0] = h0; ((uint32_t*)Clo)[i0] = l0;
                ((uint32_t*)Chi)[i1] = h1; ((uint32_t*)Clo)[i1] = l1;
            }
        }
    }
}

// ---------------------------------------------------------------------------
// Flash attention from preconverted qkv hi/lo planes.
// CTA = 128 queries x (b,h). K/V natural layout, cp.async double-buffered.
// V consumed via ldmatrix.trans (no transpose pass). Writes hi/lo bf16 planes.
// ---------------------------------------------------------------------------
#define AST 144                     // smem row stride (128B data + pad)
#define ATL (64 * AST)              // 9216 per 64x64 tile
#define ASTG (4 * ATL)              // Khi,Klo,Vhi,Vlo = 36864
#define ATTN_SMEM (2 * ASTG)        // 73728

__global__ void __launch_bounds__(256) flash2(
    const __nv_bfloat16* __restrict__ qhi, const __nv_bfloat16* __restrict__ qlo,
    __nv_bfloat16* __restrict__ ohi, __nv_bfloat16* __restrict__ olo)
{
    extern __shared__ char smem[];
    const int tid = threadIdx.x;
    const int lane = tid & 31;
    const int warp = tid >> 5;
    const int qt = blockIdx.x;
    const int bh = blockIdx.y;
    const int b = bh >> 4;
    const int h = bh & 15;

    const uint32_t sb = s2u(smem);
    const uint32_t fragoff = (uint32_t)(lane & 15) * AST + (uint32_t)(lane >> 4) * 16;
    const size_t headoff = (size_t)h * DHd;

    // K/V tile issue: row = tid>>2 (64), chunk pair = (tid&3)*2
    const int krow = tid >> 2;
    const int kcc = (tid & 3) * 2;
    auto issueKV = [&](int kb, int s) {
        const uint32_t sB = sb + s * ASTG + (uint32_t)krow * AST + kcc * 16;
        const size_t g = ((size_t)b * Ss + kb * 64 + krow) * N1 + headoff + kcc * 8;
        cp16(sB,                 qhi + g + Dd);       // K hi
        cp16(sB + 16,            qhi + g + Dd + 8);
        cp16(sB + ATL,           qlo + g + Dd);       // K lo
        cp16(sB + ATL + 16,      qlo + g + Dd + 8);
        cp16(sB + 2 * ATL,       qhi + g + 2 * Dd);   // V hi
        cp16(sB + 2 * ATL + 16,  qhi + g + 2 * Dd + 8);
        cp16(sB + 3 * ATL,       qlo + g + 2 * Dd);   // V lo
        cp16(sB + 3 * ATL + 16,  qlo + g + 2 * Dd + 8);
    };

    // preload: K/V block0 -> stage0; Q -> stage1 area
    issueKV(0, 0);
    CP_COMMIT();
    {
        const int qrow = tid >> 1;
        const int q4 = (tid & 1) * 4;
        const uint32_t sQh = sb + ASTG + (uint32_t)qrow * AST + q4 * 16;
        const uint32_t sQl = sQh + 128 * AST;
        const size_t g = ((size_t)b * Ss + qt * 128 + qrow) * N1 + headoff + q4 * 8;
#pragma unroll
        for (int i = 0; i < 4; i++) {
            cp16(sQh + i * 16, qhi + g + i * 8);
            cp16(sQl + i * 16, qlo + g + i * 8);
        }
    }
    CP_COMMIT();
    CP_WAIT0();
    __syncthreads();

    // Q fragments
    uint32_t qh[4][4], ql[4][4];
    {
        const uint32_t uQh = sb + ASTG;
        const uint32_t uQl = uQh + 128 * AST;
#pragma unroll
        for (int j = 0; j < 4; j++) {
            const uint32_t aoff = (uint32_t)(warp * 16) * AST + j * 32 + fragoff;
            ldmx4(qh[j], uQh + aoff);
            ldmx4(ql[j], uQl + aoff);
        }
    }

    float o[8][4];
    float m0 = -1e30f, m1 = -1e30f, l0 = 0.f, l1 = 0.f;
#pragma unroll
    for (int i = 0; i < 8; i++)
#pragma unroll
        for (int e = 0; e < 4; e++) o[i][e] = 0.f;

    for (int kb = 0; kb < Ss / 64; kb++) {
        const int s = kb & 1;
        if (kb > 0) CP_WAIT0();
        __syncthreads();
        if (kb + 1 < Ss / 64) {
            issueKV(kb + 1, s ^ 1);
            CP_COMMIT();
        }
        const uint32_t uKhi = sb + s * ASTG;
        const uint32_t uKlo = uKhi + ATL;
        const uint32_t uVhi = uKhi + 2 * ATL;
        const uint32_t uVlo = uKhi + 3 * ATL;

        // ---- S = Q K^T ----
        float sc[8][4];
#pragma unroll
        for (int i = 0; i < 8; i++)
#pragma unroll
            for (int e = 0; e < 4; e++) sc[i][e] = 0.f;

#pragma unroll
        for (int g = 0; g < 4; g++) {
#pragma unroll
            for (int j = 0; j < 4; j++) {
                const uint32_t boff = (uint32_t)(g * 16) * AST + j * 32 + fragoff;
                uint32_t mh[4], ml[4];
                ldmx4(mh, uKhi + boff);
                ldmx4(ml, uKlo + boff);
                uint32_t b0h[2] = {mh[0], mh[2]}, b1h[2] = {mh[1], mh[3]};
                uint32_t b0l[2] = {ml[0], ml[2]}, b1l[2] = {ml[1], ml[3]};
                mma_bf16(sc[2 * g + 0], qh[j], b0h);
                mma_bf16(sc[2 * g + 0], qh[j], b0l);
                mma_bf16(sc[2 * g + 0], ql[j], b0h);
                mma_bf16(sc[2 * g + 1], qh[j], b1h);
                mma_bf16(sc[2 * g + 1], qh[j], b1l);
                mma_bf16(sc[2 * g + 1], ql[j], b1h);
            }
        }

        // ---- online softmax ----
        float mx0 = -1e30f, mx1 = -1e30f;
#pragma unroll
        for (int i = 0; i < 8; i++) {
            mx0 = fmaxf(mx0, fmaxf(sc[i][0], sc[i][1]));
            mx1 = fmaxf(mx1, fmaxf(sc[i][2], sc[i][3]));
        }
        mx0 = fmaxf(mx0, __shfl_xor_sync(0xffffffffu, mx0, 1));
        mx0 = fmaxf(mx0, __shfl_xor_sync(0xffffffffu, mx0, 2));
        mx1 = fmaxf(mx1, __shfl_xor_sync(0xffffffffu, mx1, 1));
        mx1 = fmaxf(mx1, __shfl_xor_sync(0xffffffffu, mx1, 2));
        const float mn0 = fmaxf(m0, mx0);
        const float mn1 = fmaxf(m1, mx1);
        const float c0 = __expf(m0 - mn0);
        const float c1 = __expf(m1 - mn1);
        float rs0 = 0.f, rs1 = 0.f;
#pragma unroll
        for (int i = 0; i < 8; i++) {
            sc[i][0] = __expf(sc[i][0] - mn0);
            sc[i][1] = __expf(sc[i][1] - mn0);
            sc[i][2] = __expf(sc[i][2] - mn1);
            sc[i][3] = __expf(sc[i][3] - mn1);
            rs0 += sc[i][0] + sc[i][1];
            rs1 += sc[i][2] + sc[i][3];
        }
        rs0 += __shfl_xor_sync(0xffffffffu, rs0, 1);
        rs0 += __shfl_xor_sync(0xffffffffu, rs0, 2);
        rs1 += __shfl_xor_sync(0xffffffffu, rs1, 1);
        rs1 += __shfl_xor_sync(0xffffffffu, rs1, 2);
        l0 = l0 * c0 + rs0;
        l1 = l1 * c1 + rs1;
        m0 = mn0;
        m1 = mn1;
#pragma unroll
        for (int i = 0; i < 8; i++) {
            o[i][0] *= c0; o[i][1] *= c0;
            o[i][2] *= c1; o[i][3] *= c1;
        }

        // ---- repack P (C-frag -> A-frag) ----
        uint32_t ph[4][4], pl[4][4];
#pragma unroll
        for (int j = 0; j < 4; j++) {
            cvt_pack(sc[2 * j][0],     sc[2 * j][1],     ph[j][0], pl[j][0]);
            cvt_pack(sc[2 * j][2],     sc[2 * j][3],     ph[j][1], pl[j][1]);
            cvt_pack(sc[2 * j + 1][0], sc[2 * j + 1][1], ph[j][2], pl[j][2]);
            cvt_pack(sc[2 * j + 1][2], sc[2 * j + 1][3], ph[j][3], pl[j][3]);
        }

        // ---- O += P V  (V via trans-ldmatrix) ----
#pragma unroll
        for (int g = 0; g < 4; g++) {
#pragma unroll
            for (int j = 0; j < 4; j++) {
                const uint32_t voff = (uint32_t)(j * 16) * AST + g * 32 + fragoff;
                uint32_t mh[4], ml[4];
                ldmx4t(mh, uVhi + voff);
                ldmx4t(ml, uVlo + voff);
                uint32_t b0h[2] = {mh[0], mh[1]}, b1h[2] = {mh[2], mh[3]};
                uint32_t b0l[2] = {ml[0], ml[1]}, b1l[2] = {ml[2], ml[3]};
                mma_bf16(o[2 * g + 0], ph[j], b0h);
                mma_bf16(o[2 * g + 0], ph[j], b0l);
                mma_bf16(o[2 * g + 0], pl[j], b0h);
                mma_bf16(o[2 * g + 1], ph[j], b1h);
                mma_bf16(o[2 * g + 1], ph[j], b1l);
                mma_bf16(o[2 * g + 1], pl[j], b1h);
            }
        }
    }

    // ---- epilogue: write hi/lo planes ----
    const float inv0 = 1.f / l0;
    const float inv1 = 1.f / l1;
    const int r0 = qt * 128 + warp * 16 + (lane >> 2);
    const size_t base0 = ((size_t)b * Ss + r0) * Dd + headoff + (lane & 3) * 2;
    const size_t base1 = base0 + (size_t)8 * Dd;
#pragma unroll
    for (int nt = 0; nt < 8; nt++) {
        uint32_t h0, l0u, h1, l1u;
        cvt_pack(o[nt][0] * inv0, o[nt][1] * inv0, h0, l0u);
        cvt_pack(o[nt][2] * inv1, o[nt][3] * inv1, h1, l1u);
        ((uint32_t*)ohi)[(base0 + nt * 8) / 2] = h0;
        ((uint32_t*)olo)[(base0 + nt * 8) / 2] = l0u;
        ((uint32_t*)ohi)[(base1 + nt * 8) / 2] = h1;
        ((uint32_t*)olo)[(base1 + nt * 8) / 2] = l1u;
    }
}

// ---------------------------------------------------------------------------
extern "C" void kernel_launch(void* const* d_in, const int* in_sizes, int n_in,
                              void* d_out, int out_size)
{
    (void)in_sizes; (void)n_in; (void)out_size;
    const float* x  = (const float*)d_in[0];
    const float* w1 = (const float*)d_in[1];
    const float* b1 = (const float*)d_in[2];
    const float* w2 = (const float*)d_in[3];
    const float* b2 = (const float*)d_in[4];
    float* out = (float*)d_out;

    __nv_bfloat16 *xhi, *xlo, *w1hi, *w1lo, *w2hi, *w2lo, *qhi, *qlo, *ahi, *alo;
    cudaGetSymbolAddress((void**)&xhi, g_xhi);
    cudaGetSymbolAddress((void**)&xlo, g_xlo);
    cudaGetSymbolAddress((void**)&w1hi, g_w1hi);
    cudaGetSymbolAddress((void**)&w1lo, g_w1lo);
    cudaGetSymbolAddress((void**)&w2hi, g_w2hi);
    cudaGetSymbolAddress((void**)&w2lo, g_w2lo);
    cudaGetSymbolAddress((void**)&qhi, g_qkvhi);
    cudaGetSymbolAddress((void**)&qlo, g_qkvlo);
    cudaGetSymbolAddress((void**)&ahi, g_ahi);
    cudaGetSymbolAddress((void**)&alo, g_alo);

    cudaFuncSetAttribute(gemm_bf<0>, cudaFuncAttributeMaxDynamicSharedMemorySize, GEMM_SMEM);
    cudaFuncSetAttribute(gemm_bf<1>, cudaFuncAttributeMaxDynamicSharedMemorySize, GEMM_SMEM);
    cudaFuncSetAttribute(flash2, cudaFuncAttributeMaxDynamicSharedMemorySize, ATTN_SMEM);

    // pre-convert
    split_f32<<<(MM * Dd / 2 + 255) / 256, 256>>>(x, xhi, xlo, MM * Dd / 2);
    transpose_split<<<dim3(N1 / 32, Dd / 64), 256>>>(w1, w1hi, w1lo, Dd, N1);
    transpose_split<<<dim3(Dd / 32, Dd / 64), 256>>>(w2, w2hi, w2lo, Dd, Dd);

    // 1) QKV projection -> hi/lo planes
    gemm_bf<1><<<dim3(N1 / 128, MM / 128), 256, GEMM_SMEM>>>(
        xhi, xlo, w1hi, w1lo, b1, nullptr, qhi, qlo, MM, N1, Dd);
    // 2) attention -> hi/lo planes
    flash2<<<dim3(Ss / 128, Bb * Hh), 256, ATTN_SMEM>>>(qhi, qlo, ahi, alo);
    // 3) output projection -> fp32 out
    gemm_bf<0><<<dim3(Dd / 128, MM / 128), 256, GEMM_SMEM>>>(
        ahi, alo, w2hi, w2lo, b2, out, nullptr, nullptr, MM, Dd, Dd);
}